// round 8
// baseline (speedup 1.0000x reference)
#include <cuda_runtime.h>
#include <stdint.h>

#define N_SENS 10000
#define N_HID  400000
#define N_MOT  1000
#define E_SH   4000000
#define E_HH   16000000
#define E_HM   400000

#define SENS_WORDS 313      // ceil(10000/32)
#define HID_WORDS  12500    // 400000/32

#define G_HH (E_HH / 4)     // 4,000,000 int4 groups

// Scratch (__device__ globals; allocation-free rule)
__device__ uint32_t g_sens_bits[SENS_WORDS];
__device__ uint32_t g_hid_bits[HID_WORDS];
__device__ float    g_hid_in[N_HID];
__device__ float    g_mot_in[N_MOT];
__device__ int      g_surv_cnt;
__device__ int      g_surv[E_HH];      // worst-case capacity: no overflow possible

// ---------------------------------------------------------------------------
// K1: zero accumulators + survivor counter, build spike bitmasks
// ---------------------------------------------------------------------------
__global__ void k_init(const float* __restrict__ s_in,
                       const float* __restrict__ s_mem,
                       const float* __restrict__ prev_spk) {
    int i = blockIdx.x * blockDim.x + threadIdx.x;

    if (i == 0) g_surv_cnt = 0;
    if (i < N_HID) g_hid_in[i] = 0.0f;
    if (i < N_MOT) g_mot_in[i] = 0.0f;

    {   // hidden prev-spike bitmask (grid is multiple of 32 threads)
        int pred = (i < N_HID) ? (prev_spk[i] != 0.0f) : 0;
        uint32_t bits = __ballot_sync(0xFFFFFFFFu, pred);
        if ((i & 31) == 0 && (i >> 5) < HID_WORDS) g_hid_bits[i >> 5] = bits;
    }
    {   // sensory spike bitmask
        int pred = 0;
        if (i < N_SENS) {
            float m = 0.9f * s_mem[i] + 5.0f * s_in[i];
            pred = (m > 1.0f);
        }
        uint32_t bits = __ballot_sync(0xFFFFFFFFu, pred);
        if ((i & 31) == 0 && (i >> 5) < SENS_WORDS) g_sens_bits[i >> 5] = bits;
    }
}

// ---------------------------------------------------------------------------
// K2: SH edges, dense streaming (spikes ~89% live) — proven R5 form, unchanged
// ---------------------------------------------------------------------------
__global__ void __launch_bounds__(256, 8) k_sh(const int4* __restrict__ pre,
                                               const int4* __restrict__ post,
                                               const float4* __restrict__ w) {
    __shared__ uint32_t sb[SENS_WORDS];
    for (int i = threadIdx.x; i < SENS_WORDS; i += blockDim.x)
        sb[i] = g_sens_bits[i];
    __syncthreads();

    const int stride = gridDim.x * blockDim.x;
    for (int t = blockIdx.x * blockDim.x + threadIdx.x; t < E_SH / 4; t += stride) {
        int4 p = __ldcs(&pre[t]);
        int4 q = __ldcs(&post[t]);
        float4 wv = __ldcs(&w[t]);
        uint32_t b0 = (sb[p.x >> 5] >> (p.x & 31)) & 1u;
        uint32_t b1 = (sb[p.y >> 5] >> (p.y & 31)) & 1u;
        uint32_t b2 = (sb[p.z >> 5] >> (p.z & 31)) & 1u;
        uint32_t b3 = (sb[p.w >> 5] >> (p.w & 31)) & 1u;
        if (b0) atomicAdd(&g_hid_in[q.x], wv.x);
        if (b1) atomicAdd(&g_hid_in[q.y], wv.y);
        if (b2) atomicAdd(&g_hid_in[q.z], wv.z);
        if (b3) atomicAdd(&g_hid_in[q.w], wv.w);
    }
}

// ---------------------------------------------------------------------------
// K3a: HH scan — stream hh_pre only (64 MB), compact live edge indices.
// Warp shfl-scan + block aggregation; ONE global atomic per block-iteration.
// Trip count is block-uniform (t0 depends only on blockIdx) -> safe syncs.
// ---------------------------------------------------------------------------
#define SCAN_GRID (148 * 4)
#define SCAN_TPB  512
#define SCAN_NT   (SCAN_GRID * SCAN_TPB)

__global__ void __launch_bounds__(SCAN_TPB, 4)
k_hh_scan(const int4* __restrict__ pre) {
    extern __shared__ uint32_t hb[];            // HID_WORDS (50 KB)
    __shared__ unsigned wsum[SCAN_TPB / 32];
    __shared__ unsigned wbase[SCAN_TPB / 32];
    __shared__ unsigned blockbase;

    for (int i = threadIdx.x; i < HID_WORDS; i += blockDim.x)
        hb[i] = g_hid_bits[i];
    __syncthreads();

    const unsigned lane = threadIdx.x & 31;
    const int wid = threadIdx.x >> 5;

    for (int t0 = blockIdx.x * SCAN_TPB; t0 < G_HH; t0 += SCAN_NT) {
        int t = t0 + threadIdx.x;
        bool valid = (t < G_HH);

        uint32_t b0 = 0, b1 = 0, b2 = 0, b3 = 0;
        if (valid) {
            int4 p = __ldcs(&pre[t]);
            b0 = (hb[p.x >> 5] >> (p.x & 31)) & 1u;
            b1 = (hb[p.y >> 5] >> (p.y & 31)) & 1u;
            b2 = (hb[p.z >> 5] >> (p.z & 31)) & 1u;
            b3 = (hb[p.w >> 5] >> (p.w & 31)) & 1u;
        }
        unsigned cnt = b0 + b1 + b2 + b3;

        // warp inclusive scan of cnt
        unsigned pfx = cnt;
        #pragma unroll
        for (int d = 1; d < 32; d <<= 1) {
            unsigned v = __shfl_up_sync(0xFFFFFFFFu, pfx, d);
            if (lane >= d) pfx += v;
        }
        unsigned warp_total = __shfl_sync(0xFFFFFFFFu, pfx, 31);
        unsigned my_excl = pfx - cnt;

        if (lane == 31) wsum[wid] = warp_total;
        __syncthreads();
        if (threadIdx.x == 0) {
            unsigned s = 0;
            #pragma unroll
            for (int k = 0; k < SCAN_TPB / 32; k++) { wbase[k] = s; s += wsum[k]; }
            blockbase = s ? (unsigned)atomicAdd(&g_surv_cnt, (int)s) : 0u;
        }
        __syncthreads();

        if (cnt) {
            unsigned o = blockbase + wbase[wid] + my_excl;
            int e = 4 * t;
            if (b0) g_surv[o++] = e + 0;
            if (b1) g_surv[o++] = e + 1;
            if (b2) g_surv[o++] = e + 2;
            if (b3) g_surv[o++] = e + 3;
        }
        __syncthreads();   // protect blockbase/wsum for next iteration
    }
}

// ---------------------------------------------------------------------------
// K3b: HH apply — gather post/w for ~800K survivors, atomic accumulate.
// Independent gathers per survivor; unroll x2 for MLP.
// ---------------------------------------------------------------------------
__global__ void __launch_bounds__(512) k_hh_apply(const int* __restrict__ post,
                                                  const float* __restrict__ w) {
    const int n = g_surv_cnt;   // written by k_hh_scan (stream-ordered)
    const int stride = gridDim.x * blockDim.x;
    int i = blockIdx.x * blockDim.x + threadIdx.x;
    for (; i + stride < n; i += 2 * stride) {
        int e0 = g_surv[i];
        int e1 = g_surv[i + stride];
        int q0 = __ldg(&post[e0]);
        float w0 = __ldg(&w[e0]);
        int q1 = __ldg(&post[e1]);
        float w1 = __ldg(&w[e1]);
        atomicAdd(&g_hid_in[q0], 0.5f * w0);
        atomicAdd(&g_hid_in[q1], 0.5f * w1);
    }
    if (i < n) {
        int e = g_surv[i];
        atomicAdd(&g_hid_in[__ldg(&post[e])], 0.5f * __ldg(&w[e]));
    }
}

// ---------------------------------------------------------------------------
// K5: HM edges -> mot_in, hidden spike computed INLINE from h_mem + g_hid_in
// (eliminates the separate k_hid_spike kernel).
// ---------------------------------------------------------------------------
__global__ void k_hm(const float* __restrict__ h_mem,
                     const int4* __restrict__ pre,
                     const int4* __restrict__ post,
                     const float4* __restrict__ w) {
    int t = blockIdx.x * blockDim.x + threadIdx.x;
    if (t >= E_HM / 4) return;
    int4 p = __ldcs(&pre[t]);
    int4 q = __ldcs(&post[t]);
    float4 wv = __ldcs(&w[t]);
    bool s0 = 0.9f * __ldg(&h_mem[p.x]) + 5.0f * g_hid_in[p.x] > 1.0f;
    bool s1 = 0.9f * __ldg(&h_mem[p.y]) + 5.0f * g_hid_in[p.y] > 1.0f;
    bool s2 = 0.9f * __ldg(&h_mem[p.z]) + 5.0f * g_hid_in[p.z] > 1.0f;
    bool s3 = 0.9f * __ldg(&h_mem[p.w]) + 5.0f * g_hid_in[p.w] > 1.0f;
    if (s0) atomicAdd(&g_mot_in[q.x], wv.x);
    if (s1) atomicAdd(&g_mot_in[q.y], wv.y);
    if (s2) atomicAdd(&g_mot_in[q.z], wv.z);
    if (s3) atomicAdd(&g_mot_in[q.w], wv.w);
}

// ---------------------------------------------------------------------------
// K6: motor LIF -> output
// ---------------------------------------------------------------------------
__global__ void k_mot(const float* __restrict__ m_mem, float* __restrict__ out) {
    int i = blockIdx.x * blockDim.x + threadIdx.x;
    if (i >= N_MOT) return;
    float m = 0.9f * m_mem[i] + 20.0f * g_mot_in[i];
    out[i] = (m > 1.0f) ? 1.0f : 0.0f;
}

extern "C" void kernel_launch(void* const* d_in, const int* in_sizes, int n_in,
                              void* d_out, int out_size) {
    const float* sensory_input     = (const float*)d_in[0];
    const float* sensory_mem       = (const float*)d_in[1];
    const float* hidden_mem        = (const float*)d_in[2];
    const float* motor_mem         = (const float*)d_in[3];
    const float* hidden_prev_spike = (const float*)d_in[4];
    const float* w_sh              = (const float*)d_in[5];
    const float* w_hh              = (const float*)d_in[6];
    const float* w_hm              = (const float*)d_in[7];
    const int*   sh_pre            = (const int*)d_in[8];
    const int*   sh_post           = (const int*)d_in[9];
    const int*   hh_pre            = (const int*)d_in[10];
    const int*   hh_post           = (const int*)d_in[11];
    const int*   hm_pre            = (const int*)d_in[12];
    const int*   hm_post           = (const int*)d_in[13];
    float* out = (float*)d_out;

    static bool once = false;
    static cudaStream_t s1;
    static cudaEvent_t ev_fork, ev_join;
    const int hh_smem = HID_WORDS * sizeof(uint32_t);  // 50000 bytes
    if (!once) {
        cudaFuncSetAttribute(k_hh_scan,
                             cudaFuncAttributeMaxDynamicSharedMemorySize, hh_smem);
        cudaStreamCreateWithFlags(&s1, cudaStreamNonBlocking);
        cudaEventCreateWithFlags(&ev_fork, cudaEventDisableTiming);
        cudaEventCreateWithFlags(&ev_join, cudaEventDisableTiming);
        once = true;
    }

    // init on the main (captured) stream
    k_init<<<(N_HID + 255) / 256, 256>>>(sensory_input, sensory_mem,
                                         hidden_prev_spike);

    // fork: SH runs on side stream concurrently with HH scan+apply on main
    cudaEventRecord(ev_fork, 0);
    cudaStreamWaitEvent(s1, ev_fork, 0);

    k_sh<<<148 * 8, 256, 0, s1>>>((const int4*)sh_pre, (const int4*)sh_post,
                                  (const float4*)w_sh);

    k_hh_scan<<<SCAN_GRID, SCAN_TPB, hh_smem>>>((const int4*)hh_pre);
    k_hh_apply<<<148 * 4, 512>>>(hh_post, w_hh);

    // join: main stream waits for SH before g_hid_in is consumed
    cudaEventRecord(ev_join, s1);
    cudaStreamWaitEvent(0, ev_join, 0);

    k_hm<<<(E_HM / 4 + 255) / 256, 256>>>(hidden_mem,
                                          (const int4*)hm_pre,
                                          (const int4*)hm_post,
                                          (const float4*)w_hm);

    k_mot<<<(N_MOT + 255) / 256, 256>>>(motor_mem, out);
}

// round 9
// speedup vs baseline: 1.0855x; 1.0855x over previous
#include <cuda_runtime.h>
#include <stdint.h>

#define N_SENS 10000
#define N_HID  400000
#define N_MOT  1000
#define E_SH   4000000
#define E_HH   16000000
#define E_HM   400000

#define SENS_WORDS 313      // ceil(10000/32)
#define HID_WORDS  12500    // 400000/32

#define G_SH (E_SH / 4)     // 1,000,000 int4 groups
#define G_HH (E_HH / 4)     // 4,000,000

#define EGRID 592           // 148 SMs x 4 blocks, all co-resident
#define ETPB  512
#define N_SH_BLK (EGRID / 4)          // 148 blocks -> SH role
#define N_HH_BLK (EGRID - N_SH_BLK)   // 444 blocks -> HH role

// Scratch (__device__ globals; allocation-free rule)
__device__ uint32_t g_sens_bits[SENS_WORDS];
__device__ uint32_t g_hid_bits[HID_WORDS];
__device__ float    g_hid_in[N_HID];
__device__ float    g_mot_in[N_MOT];

// ---------------------------------------------------------------------------
// K1: zero accumulators, build sensory + hidden-prev spike bitmasks
// ---------------------------------------------------------------------------
__global__ void k_init(const float* __restrict__ s_in,
                       const float* __restrict__ s_mem,
                       const float* __restrict__ prev_spk) {
    int i = blockIdx.x * blockDim.x + threadIdx.x;

    if (i < N_HID) g_hid_in[i] = 0.0f;
    if (i < N_MOT) g_mot_in[i] = 0.0f;

    {   // hidden prev-spike bitmask (grid is multiple of 32 threads)
        int pred = (i < N_HID) ? (prev_spk[i] != 0.0f) : 0;
        uint32_t bits = __ballot_sync(0xFFFFFFFFu, pred);
        if ((i & 31) == 0 && (i >> 5) < HID_WORDS) g_hid_bits[i >> 5] = bits;
    }
    {   // sensory spike bitmask
        int pred = 0;
        if (i < N_SENS) {
            float m = 0.9f * s_mem[i] + 5.0f * s_in[i];
            pred = (m > 1.0f);
        }
        uint32_t bits = __ballot_sync(0xFFFFFFFFu, pred);
        if ((i & 31) == 0 && (i >> 5) < SENS_WORDS) g_sens_bits[i >> 5] = bits;
    }
}

// ---------------------------------------------------------------------------
// K2: role-split edge kernel. Every SM hosts 4 co-resident blocks:
//   3 blocks stream HH (192 MB), 1 block streams SH (48 MB).
// Dense streaming in both roles: 3 independent LDG.128 per iteration,
// smem bitmask gates predicated atomics (RED, no return value).
// ---------------------------------------------------------------------------
__global__ void __launch_bounds__(ETPB, 4)
k_edges(const int4* __restrict__ sh_pre,
        const int4* __restrict__ sh_post,
        const float4* __restrict__ sh_w,
        const int4* __restrict__ hh_pre,
        const int4* __restrict__ hh_post,
        const float4* __restrict__ hh_w) {
    extern __shared__ uint32_t bits[];     // 50 KB: hid mask (HH) or sens mask (SH)
    const int b = blockIdx.x;
    const bool is_sh = ((b & 3) == 3);

    if (is_sh) {
        for (int i = threadIdx.x; i < SENS_WORDS; i += blockDim.x)
            bits[i] = g_sens_bits[i];
    } else {
        for (int i = threadIdx.x; i < HID_WORDS; i += blockDim.x)
            bits[i] = g_hid_bits[i];
    }
    __syncthreads();

    if (is_sh) {
        const int rank = b >> 2;                      // 0..147
        const int stride = N_SH_BLK * ETPB;
        for (int t = rank * ETPB + threadIdx.x; t < G_SH; t += stride) {
            int4 p = __ldcs(&sh_pre[t]);
            int4 q = __ldcs(&sh_post[t]);
            float4 wv = __ldcs(&sh_w[t]);
            uint32_t b0 = (bits[p.x >> 5] >> (p.x & 31)) & 1u;
            uint32_t b1 = (bits[p.y >> 5] >> (p.y & 31)) & 1u;
            uint32_t b2 = (bits[p.z >> 5] >> (p.z & 31)) & 1u;
            uint32_t b3 = (bits[p.w >> 5] >> (p.w & 31)) & 1u;
            if (b0) atomicAdd(&g_hid_in[q.x], wv.x);
            if (b1) atomicAdd(&g_hid_in[q.y], wv.y);
            if (b2) atomicAdd(&g_hid_in[q.z], wv.z);
            if (b3) atomicAdd(&g_hid_in[q.w], wv.w);
        }
    } else {
        const int rank = b - (b >> 2);                // 0..443 over non-SH blocks
        const int stride = N_HH_BLK * ETPB;
        for (int t = rank * ETPB + threadIdx.x; t < G_HH; t += stride) {
            int4 p = __ldcs(&hh_pre[t]);
            int4 q = __ldcs(&hh_post[t]);
            float4 wv = __ldcs(&hh_w[t]);
            uint32_t b0 = (bits[p.x >> 5] >> (p.x & 31)) & 1u;
            uint32_t b1 = (bits[p.y >> 5] >> (p.y & 31)) & 1u;
            uint32_t b2 = (bits[p.z >> 5] >> (p.z & 31)) & 1u;
            uint32_t b3 = (bits[p.w >> 5] >> (p.w & 31)) & 1u;
            if (b0) atomicAdd(&g_hid_in[q.x], 0.5f * wv.x);
            if (b1) atomicAdd(&g_hid_in[q.y], 0.5f * wv.y);
            if (b2) atomicAdd(&g_hid_in[q.z], 0.5f * wv.z);
            if (b3) atomicAdd(&g_hid_in[q.w], 0.5f * wv.w);
        }
    }
}

// ---------------------------------------------------------------------------
// K3: HM edges -> mot_in, hidden spike computed inline (proven R7 form)
// ---------------------------------------------------------------------------
__global__ void k_hm(const float* __restrict__ h_mem,
                     const int4* __restrict__ pre,
                     const int4* __restrict__ post,
                     const float4* __restrict__ w) {
    int t = blockIdx.x * blockDim.x + threadIdx.x;
    if (t >= E_HM / 4) return;
    int4 p = __ldcs(&pre[t]);
    int4 q = __ldcs(&post[t]);
    float4 wv = __ldcs(&w[t]);
    bool s0 = 0.9f * __ldg(&h_mem[p.x]) + 5.0f * g_hid_in[p.x] > 1.0f;
    bool s1 = 0.9f * __ldg(&h_mem[p.y]) + 5.0f * g_hid_in[p.y] > 1.0f;
    bool s2 = 0.9f * __ldg(&h_mem[p.z]) + 5.0f * g_hid_in[p.z] > 1.0f;
    bool s3 = 0.9f * __ldg(&h_mem[p.w]) + 5.0f * g_hid_in[p.w] > 1.0f;
    if (s0) atomicAdd(&g_mot_in[q.x], wv.x);
    if (s1) atomicAdd(&g_mot_in[q.y], wv.y);
    if (s2) atomicAdd(&g_mot_in[q.z], wv.z);
    if (s3) atomicAdd(&g_mot_in[q.w], wv.w);
}

// ---------------------------------------------------------------------------
// K4: motor LIF -> output
// ---------------------------------------------------------------------------
__global__ void k_mot(const float* __restrict__ m_mem, float* __restrict__ out) {
    int i = blockIdx.x * blockDim.x + threadIdx.x;
    if (i >= N_MOT) return;
    float m = 0.9f * m_mem[i] + 20.0f * g_mot_in[i];
    out[i] = (m > 1.0f) ? 1.0f : 0.0f;
}

extern "C" void kernel_launch(void* const* d_in, const int* in_sizes, int n_in,
                              void* d_out, int out_size) {
    const float* sensory_input     = (const float*)d_in[0];
    const float* sensory_mem       = (const float*)d_in[1];
    const float* hidden_mem        = (const float*)d_in[2];
    const float* motor_mem         = (const float*)d_in[3];
    const float* hidden_prev_spike = (const float*)d_in[4];
    const float* w_sh              = (const float*)d_in[5];
    const float* w_hh              = (const float*)d_in[6];
    const float* w_hm              = (const float*)d_in[7];
    const int*   sh_pre            = (const int*)d_in[8];
    const int*   sh_post           = (const int*)d_in[9];
    const int*   hh_pre            = (const int*)d_in[10];
    const int*   hh_post           = (const int*)d_in[11];
    const int*   hm_pre            = (const int*)d_in[12];
    const int*   hm_post           = (const int*)d_in[13];
    float* out = (float*)d_out;

    static bool once = false;
    const int smem = HID_WORDS * sizeof(uint32_t);  // 50000 bytes
    if (!once) {
        cudaFuncSetAttribute(k_edges,
                             cudaFuncAttributeMaxDynamicSharedMemorySize, smem);
        once = true;
    }

    k_init<<<(N_HID + 255) / 256, 256>>>(sensory_input, sensory_mem,
                                         hidden_prev_spike);

    k_edges<<<EGRID, ETPB, smem>>>(
        (const int4*)sh_pre, (const int4*)sh_post, (const float4*)w_sh,
        (const int4*)hh_pre, (const int4*)hh_post, (const float4*)w_hh);

    k_hm<<<(E_HM / 4 + 255) / 256, 256>>>(hidden_mem,
                                          (const int4*)hm_pre,
                                          (const int4*)hm_post,
                                          (const float4*)w_hm);

    k_mot<<<(N_MOT + 255) / 256, 256>>>(motor_mem, out);
}